// round 4
// baseline (speedup 1.0000x reference)
#include <cuda_runtime.h>
#include <math.h>

// Problem constants
#define N_TOKENS    16384
#define MODEL_DIM   2048
#define NUM_EXPERTS 64
#define TOPK        2
#define NK          (N_TOKENS * TOPK)      // 32768

// GEMM tiling: 128 tokens x 64 experts per block, 256 threads, 8x4 per thread
#define BT    128
#define DK    16
#define NBLK  (N_TOKENS / BT)              // 128 blocks
#define CHUNK (BT * TOPK)                  // 256 slots per chunk

// Output layout (concatenated float32, reference return order)
#define OFF_TOKEN  0
#define OFF_REV    (NK)
#define OFF_CW     (2 * NK)
#define OFF_SPLITS (3 * NK)
#define OFF_PROBS  (3 * NK + NUM_EXPERTS)

// Scratch (no allocation allowed -> device globals)
__device__ int g_flat_idx[NK];
__device__ int g_hist[NBLK][NUM_EXPERTS];
__device__ int g_offset[NBLK][NUM_EXPERTS];

// ---------------------------------------------------------------------------
// Kernel 1: fp32 gate GEMM + softmax + top-2 + combine weights + chunk hist
// ---------------------------------------------------------------------------
__global__ __launch_bounds__(256) void gate_kernel(
    const float* __restrict__ X,    // [N_TOKENS, MODEL_DIM]
    const float* __restrict__ W,    // [NUM_EXPERTS, MODEL_DIM]
    float* __restrict__ out)
{
    __shared__ union SU {
        struct {
            float As[DK][BT + 4];            // 16 x 132
            float Bs[DK][NUM_EXPERTS + 4];   // 16 x 68
        } mm;
        float logits[BT][NUM_EXPERTS + 1];   // 128 x 65
    } sm;
    __shared__ int s_hist[NUM_EXPERTS];

    const int tid = threadIdx.x;
    const int b   = blockIdx.x;
    const int t0  = b * BT;
    const int tx  = tid & 15;   // expert group: experts [tx*4, tx*4+4)
    const int ty  = tid >> 4;   // token  group: tokens  [ty*8, ty*8+8)

    if (tid < NUM_EXPERTS) s_hist[tid] = 0;

    float acc[8][4];
#pragma unroll
    for (int i = 0; i < 8; i++)
#pragma unroll
        for (int j = 0; j < 4; j++) acc[i][j] = 0.0f;

    for (int k0 = 0; k0 < MODEL_DIM; k0 += DK) {
        // Load A tile: 128 rows x 16 cols = 512 float4, 2 per thread
#pragma unroll
        for (int l = 0; l < 2; l++) {
            int i = tid + l * 256;
            int t = i >> 2;
            int q = i & 3;
            float4 v = *(const float4*)(X + (size_t)(t0 + t) * MODEL_DIM + k0 + q * 4);
            sm.mm.As[q * 4 + 0][t] = v.x;
            sm.mm.As[q * 4 + 1][t] = v.y;
            sm.mm.As[q * 4 + 2][t] = v.z;
            sm.mm.As[q * 4 + 3][t] = v.w;
        }
        // Load B tile: 64 rows x 16 cols = 256 float4, 1 per thread
        {
            int t = tid >> 2;
            int q = tid & 3;
            float4 v = *(const float4*)(W + (size_t)t * MODEL_DIM + k0 + q * 4);
            sm.mm.Bs[q * 4 + 0][t] = v.x;
            sm.mm.Bs[q * 4 + 1][t] = v.y;
            sm.mm.Bs[q * 4 + 2][t] = v.z;
            sm.mm.Bs[q * 4 + 3][t] = v.w;
        }
        __syncthreads();

#pragma unroll
        for (int kk = 0; kk < DK; kk++) {
            float a[8], bv[4];
#pragma unroll
            for (int i = 0; i < 8; i++) a[i] = sm.mm.As[kk][ty * 8 + i];
#pragma unroll
            for (int j = 0; j < 4; j++) bv[j] = sm.mm.Bs[kk][tx * 4 + j];
#pragma unroll
            for (int i = 0; i < 8; i++)
#pragma unroll
                for (int j = 0; j < 4; j++) acc[i][j] = fmaf(a[i], bv[j], acc[i][j]);
        }
        __syncthreads();
    }

    // Dump logits to shared (mm region is dead now; last sync protects aliasing)
#pragma unroll
    for (int i = 0; i < 8; i++)
#pragma unroll
        for (int j = 0; j < 4; j++)
            sm.logits[ty * 8 + i][tx * 4 + j] = acc[i][j];
    __syncthreads();

    // Phase 2: one thread per token (first 128 threads)
    if (tid < BT) {
        const int t = tid;
        float* row = sm.logits[t];

        // argmax (strict >, lowest index on ties == lax.top_k)
        float m1 = -INFINITY; int e1 = 0;
#pragma unroll
        for (int e = 0; e < NUM_EXPERTS; e++) {
            float v = row[e];
            if (v > m1) { m1 = v; e1 = e; }
        }
        float m2 = -INFINITY; int e2 = 0;
#pragma unroll
        for (int e = 0; e < NUM_EXPERTS; e++) {
            float v = row[e];
            if (e != e1 && v > m2) { m2 = v; e2 = e; }
        }

        // stable softmax over 64 logits, store probs back into row
        float s = 0.0f;
#pragma unroll
        for (int e = 0; e < NUM_EXPERTS; e++) {
            float ex = expf(row[e] - m1);
            row[e] = ex;
            s += ex;
        }
        float inv = 1.0f / s;
#pragma unroll
        for (int e = 0; e < NUM_EXPERTS; e++) row[e] *= inv;

        float p1 = row[e1];
        float p2 = row[e2];
        // combine = softmax([p1, p2]) with p1 >= p2
        float r  = expf(p2 - p1);
        float c1 = 1.0f / (1.0f + r);
        float c2 = r * c1;

        int gi = 2 * (t0 + t);
        g_flat_idx[gi]     = e1;
        g_flat_idx[gi + 1] = e2;
        out[OFF_CW + gi]     = c1;
        out[OFF_CW + gi + 1] = c2;

        atomicAdd(&s_hist[e1], 1);
        atomicAdd(&s_hist[e2], 1);
    }
    __syncthreads();

    // Coalesced probs writeout: 128 x 64 floats
    for (int i = tid; i < BT * NUM_EXPERTS; i += 256) {
        out[OFF_PROBS + (size_t)t0 * NUM_EXPERTS + i] =
            sm.logits[i >> 6][i & 63];
    }
    if (tid < NUM_EXPERTS) g_hist[b][tid] = s_hist[tid];
}

// ---------------------------------------------------------------------------
// Kernel 2: per-expert chunk-prefix + expert base offsets + input_splits
// ---------------------------------------------------------------------------
__global__ void prefix_kernel(float* __restrict__ out)
{
    __shared__ int s_cnt[NUM_EXPERTS];
    __shared__ int s_base[NUM_EXPERTS];
    const int e = threadIdx.x;

    int run = 0;
#pragma unroll 8
    for (int c = 0; c < NBLK; c++) {
        g_offset[c][e] = run;
        run += g_hist[c][e];
    }
    s_cnt[e] = run;
    __syncthreads();
    if (e == 0) {
        int base = 0;
        for (int i = 0; i < NUM_EXPERTS; i++) { s_base[i] = base; base += s_cnt[i]; }
    }
    __syncthreads();
    out[OFF_SPLITS + e] = (float)s_cnt[e];
    const int be = s_base[e];
#pragma unroll 8
    for (int c = 0; c < NBLK; c++) g_offset[c][e] += be;
}

// ---------------------------------------------------------------------------
// Kernel 3: stable scatter (counting sort) -> token_order, reversed_ordering
// ---------------------------------------------------------------------------
__global__ __launch_bounds__(CHUNK) void scatter_kernel(float* __restrict__ out)
{
    __shared__ int s_e[CHUNK];
    const int tid = threadIdx.x;
    const int b   = blockIdx.x;
    const int gi  = b * CHUNK + tid;

    const int me = g_flat_idx[gi];
    s_e[tid] = me;
    __syncthreads();

    // stable in-chunk rank: # of earlier slots with the same expert
    int r = 0;
#pragma unroll 16
    for (int j = 0; j < CHUNK; j++) {
        r += (int)((j < tid) & (s_e[j] == me));
    }
    const int pos = g_offset[b][me] + r;

    out[OFF_TOKEN + pos] = (float)(gi >> 1);   // token index
    out[OFF_REV + gi]    = (float)pos;         // reversed ordering
}

// ---------------------------------------------------------------------------
extern "C" void kernel_launch(void* const* d_in, const int* in_sizes, int n_in,
                              void* d_out, int out_size)
{
    const float* X = (const float*)d_in[0];   // inputs [16384, 2048]
    const float* W = (const float*)d_in[1];   // wg_weight [64, 2048]
    float* out = (float*)d_out;

    gate_kernel<<<NBLK, 256>>>(X, W, out);
    prefix_kernel<<<1, NUM_EXPERTS>>>(out);
    scatter_kernel<<<NBLK, CHUNK>>>(out);
}

// round 8
// speedup vs baseline: 3.5303x; 3.5303x over previous
#include <cuda_runtime.h>
#include <cuda_bf16.h>
#include <math.h>
#include <stdint.h>

// Problem constants
#define N_TOKENS    16384
#define MODEL_DIM   2048
#define NUM_EXPERTS 64
#define TOPK        2
#define NK          (N_TOKENS * TOPK)      // 32768

#define BT    128                          // tokens per CTA
#define NBLK  (N_TOKENS / BT)              // 128 CTAs
#define KC    64                           // K elements per chunk (128B bf16 rows)
#define NCHUNK (MODEL_DIM / KC)            // 32
#define CHUNK (BT * TOPK)                  // 256 slots per scatter chunk

// Output layout (concatenated float32, reference return order)
#define OFF_TOKEN  0
#define OFF_REV    (NK)
#define OFF_CW     (2 * NK)
#define OFF_SPLITS (3 * NK)
#define OFF_PROBS  (3 * NK + NUM_EXPERTS)

// Stage layout inside dynamic SMEM (per stage, 1024B aligned)
#define A_HI_OFF   0
#define A_LO_OFF   16384
#define B_HI_OFF   32768
#define B_LO_OFF   40960
#define STAGE_BYTES 49152                   // 48KB
#define SMEM_DYN   (1024 + 2 * STAGE_BYTES)

// Scratch globals (no allocation allowed)
__device__ int g_flat_idx[NK];
__device__ int g_hist[NBLK][NUM_EXPERTS];
__device__ int g_offset[NBLK][NUM_EXPERTS];
__device__ __align__(16) __nv_bfloat16 g_Whi[NUM_EXPERTS * MODEL_DIM];
__device__ __align__(16) __nv_bfloat16 g_Wlo[NUM_EXPERTS * MODEL_DIM];

// ---------------------------------------------------------------------------
// Helpers (sm_80-compatible PTX only: ldmatrix + mma.sync — no tcgen05)
// ---------------------------------------------------------------------------
#define SMEM_SWIZZLE_128B(o) ((o) ^ (((o) >> 3) & 0x70u))

__device__ __forceinline__ uint32_t smem_to_u32(const void* p) {
    uint32_t a;
    asm("{ .reg .u64 t; cvta.to.shared.u64 t, %1; cvt.u32.u64 %0, t; }"
        : "=r"(a) : "l"(p));
    return a;
}

__device__ __forceinline__ void ldm_x4(uint32_t* r, uint32_t addr) {
    asm volatile("ldmatrix.sync.aligned.m8n8.x4.shared.b16 {%0,%1,%2,%3}, [%4];"
                 : "=r"(r[0]), "=r"(r[1]), "=r"(r[2]), "=r"(r[3]) : "r"(addr));
}

__device__ __forceinline__ void mma16816(float* c, const uint32_t* a,
                                         uint32_t b0, uint32_t b1) {
    asm volatile(
        "mma.sync.aligned.m16n8k16.row.col.f32.bf16.bf16.f32 "
        "{%0,%1,%2,%3}, {%4,%5,%6,%7}, {%8,%9}, {%0,%1,%2,%3};"
        : "+f"(c[0]), "+f"(c[1]), "+f"(c[2]), "+f"(c[3])
        : "r"(a[0]), "r"(a[1]), "r"(a[2]), "r"(a[3]), "r"(b0), "r"(b1));
}

// split one fp32 pair into bf16x2 hi and residual bf16x2 lo (x0 in low half)
__device__ __forceinline__ void cvt_pair(float x0, float x1,
                                         uint32_t& hi2, uint32_t& lo2) {
    asm("cvt.rn.bf16x2.f32 %0, %1, %2;" : "=r"(hi2) : "f"(x1), "f"(x0));
    float h0 = __uint_as_float(hi2 << 16);
    float h1 = __uint_as_float(hi2 & 0xffff0000u);
    float r0 = x0 - h0;
    float r1 = x1 - h1;
    asm("cvt.rn.bf16x2.f32 %0, %1, %2;" : "=r"(lo2) : "f"(r1), "f"(r0));
}

__device__ __forceinline__ void sts64(uint32_t addr, uint32_t a, uint32_t b) {
    asm volatile("st.shared.v2.b32 [%0], {%1, %2};"
                 :: "r"(addr), "r"(a), "r"(b) : "memory");
}
__device__ __forceinline__ void sts128(uint32_t addr, uint4 v) {
    asm volatile("st.shared.v4.b32 [%0], {%1, %2, %3, %4};"
                 :: "r"(addr), "r"(v.x), "r"(v.y), "r"(v.z), "r"(v.w) : "memory");
}

// ---------------------------------------------------------------------------
// Kernel 0: convert W fp32 -> bf16 hi/lo (64 x 2048, one float4 per thread)
// ---------------------------------------------------------------------------
__global__ __launch_bounds__(256) void wconv_kernel(const float* __restrict__ W)
{
    int idx = blockIdx.x * 256 + threadIdx.x;      // 0 .. 32767
    float4 v = *(const float4*)(W + (size_t)idx * 4);
    uint32_t h0, l0, h1, l1;
    cvt_pair(v.x, v.y, h0, l0);
    cvt_pair(v.z, v.w, h1, l1);
    ((uint2*)g_Whi)[idx] = make_uint2(h0, h1);
    ((uint2*)g_Wlo)[idx] = make_uint2(l0, l1);
}

// ---------------------------------------------------------------------------
// Kernel 1: HMMA split-bf16 gate GEMM + softmax + top-2 + chunk hist
// ---------------------------------------------------------------------------
__global__ __launch_bounds__(256, 1) void gate_kernel(
    const float* __restrict__ X,    // [N_TOKENS, MODEL_DIM]
    float* __restrict__ out)
{
    extern __shared__ char dsm[];
    __shared__ int s_hist[NUM_EXPERTS];

    const int tid  = threadIdx.x;
    const int lane = tid & 31;
    const int w    = tid >> 5;
    const int b    = blockIdx.x;
    const int t0   = b * BT;

    uint32_t smem_raw = smem_to_u32(dsm);
    const uint32_t tile0 = (smem_raw + 1023) & ~1023u;
    float (*logits)[NUM_EXPERTS + 1] = (float(*)[NUM_EXPERTS + 1])(dsm + (tile0 - smem_raw));

    if (tid < NUM_EXPERTS) s_hist[tid] = 0;

    // Warp tile: 32 tokens x 32 experts
    const int wm = (w & 3) * 32;        // token rows
    const int wn = (w >> 2) * 32;       // expert cols

    // ldmatrix per-lane addressing (constant across chunks except buffer base)
    // A fragments (m16k16): row = wm + 16*mi + (lane&15), koff = +16 for lanes>=16
    const uint32_t a_row  = (uint32_t)(lane & 15);
    const uint32_t a_koff = (uint32_t)((lane >> 4) << 4);
    // B fragments (x4 = two n8-tiles): row n = wn + 16*bi + (lane&7) + ((lane&16)?8:0)
    const uint32_t b_row  = (uint32_t)((lane & 7) + ((lane & 16) ? 8 : 0));
    const uint32_t b_koff = (uint32_t)((lane & 8) ? 16 : 0);

    float acc[2][4][4];
#pragma unroll
    for (int mi = 0; mi < 2; mi++)
#pragma unroll
        for (int j = 0; j < 4; j++)
#pragma unroll
            for (int q = 0; q < 4; q++) acc[mi][j][q] = 0.0f;

    // Prefetch registers
    float4 pa[8];
    uint4  pbh[2], pbl[2];

    // prologue: fetch chunk 0
    {
        const int k0 = 0;
#pragma unroll
        for (int l = 0; l < 8; l++) {
            int i = l * 256 + tid;
            int row = i >> 4, q = i & 15;
            pa[l] = *(const float4*)(X + (size_t)(t0 + row) * MODEL_DIM + k0 + q * 4);
        }
#pragma unroll
        for (int l = 0; l < 2; l++) {
            int i = l * 256 + tid;
            int row = i >> 3, u = i & 7;
            pbh[l] = *(const uint4*)((const char*)g_Whi + ((size_t)row * MODEL_DIM + k0) * 2 + u * 16);
            pbl[l] = *(const uint4*)((const char*)g_Wlo + ((size_t)row * MODEL_DIM + k0) * 2 + u * 16);
        }
    }

    for (int c = 0; c < NCHUNK; c++) {
        const uint32_t sb = tile0 + (uint32_t)(c & 1) * STAGE_BYTES;

        // convert + store prefetched chunk c into SMEM stage
#pragma unroll
        for (int l = 0; l < 8; l++) {
            int i = l * 256 + tid;
            int row = i >> 4, q = i & 15;
            uint32_t h0, l0v, h1, l1v;
            cvt_pair(pa[l].x, pa[l].y, h0, l0v);
            cvt_pair(pa[l].z, pa[l].w, h1, l1v);
            uint32_t off = SMEM_SWIZZLE_128B((uint32_t)(row * 128 + q * 8));
            sts64(sb + A_HI_OFF + off, h0, h1);
            sts64(sb + A_LO_OFF + off, l0v, l1v);
        }
#pragma unroll
        for (int l = 0; l < 2; l++) {
            int i = l * 256 + tid;
            int row = i >> 3, u = i & 7;
            uint32_t off = SMEM_SWIZZLE_128B((uint32_t)(row * 128 + u * 16));
            sts128(sb + B_HI_OFF + off, pbh[l]);
            sts128(sb + B_LO_OFF + off, pbl[l]);
        }

        // issue prefetch for chunk c+1 (overlaps with MMA below)
        if (c + 1 < NCHUNK) {
            const int k0 = (c + 1) * KC;
#pragma unroll
            for (int l = 0; l < 8; l++) {
                int i = l * 256 + tid;
                int row = i >> 4, q = i & 15;
                pa[l] = *(const float4*)(X + (size_t)(t0 + row) * MODEL_DIM + k0 + q * 4);
            }
#pragma unroll
            for (int l = 0; l < 2; l++) {
                int i = l * 256 + tid;
                int row = i >> 3, u = i & 7;
                pbh[l] = *(const uint4*)((const char*)g_Whi + ((size_t)row * MODEL_DIM + k0) * 2 + u * 16);
                pbl[l] = *(const uint4*)((const char*)g_Wlo + ((size_t)row * MODEL_DIM + k0) * 2 + u * 16);
            }
        }
        __syncthreads();

        // compute: 4 k-steps of k16 over this chunk
#pragma unroll
        for (int kk = 0; kk < 4; kk++) {
            uint32_t ah[2][4], al[2][4];
#pragma unroll
            for (int mi = 0; mi < 2; mi++) {
                uint32_t ro = (uint32_t)((wm + 16 * mi + a_row) * 128) + kk * 32 + a_koff;
                uint32_t sw = SMEM_SWIZZLE_128B(ro);
                ldm_x4(ah[mi], sb + A_HI_OFF + sw);
                ldm_x4(al[mi], sb + A_LO_OFF + sw);
            }
            uint32_t bh[2][4], bl[2][4];
#pragma unroll
            for (int bi = 0; bi < 2; bi++) {
                uint32_t ro = (uint32_t)((wn + 16 * bi + b_row) * 128) + kk * 32 + b_koff;
                uint32_t sw = SMEM_SWIZZLE_128B(ro);
                ldm_x4(bh[bi], sb + B_HI_OFF + sw);
                ldm_x4(bl[bi], sb + B_LO_OFF + sw);
            }
#pragma unroll
            for (int mi = 0; mi < 2; mi++) {
#pragma unroll
                for (int j = 0; j < 4; j++) {
                    const int bi = j >> 1, sel = (j & 1) * 2;
                    mma16816(acc[mi][j], ah[mi], bh[bi][sel], bh[bi][sel + 1]);
                    mma16816(acc[mi][j], ah[mi], bl[bi][sel], bl[bi][sel + 1]);
                    mma16816(acc[mi][j], al[mi], bh[bi][sel], bh[bi][sel + 1]);
                }
            }
        }
        __syncthreads();
    }

    // Dump accumulators -> SMEM logits [128][65]
#pragma unroll
    for (int mi = 0; mi < 2; mi++) {
        int r0 = wm + 16 * mi + (lane >> 2);
#pragma unroll
        for (int j = 0; j < 4; j++) {
            int col = wn + j * 8 + 2 * (lane & 3);
            logits[r0][col]         = acc[mi][j][0];
            logits[r0][col + 1]     = acc[mi][j][1];
            logits[r0 + 8][col]     = acc[mi][j][2];
            logits[r0 + 8][col + 1] = acc[mi][j][3];
        }
    }
    __syncthreads();

    // Phase 2: one thread per token (first 128 threads)
    if (tid < BT) {
        float* row = logits[tid];
        const int token = t0 + tid;

        float m1 = -INFINITY; int e1 = 0;
#pragma unroll
        for (int e = 0; e < NUM_EXPERTS; e++) {
            float v = row[e];
            if (v > m1) { m1 = v; e1 = e; }
        }
        float m2 = -INFINITY; int e2 = 0;
#pragma unroll
        for (int e = 0; e < NUM_EXPERTS; e++) {
            float v = row[e];
            if (e != e1 && v > m2) { m2 = v; e2 = e; }
        }

        float s = 0.0f;
#pragma unroll
        for (int e = 0; e < NUM_EXPERTS; e++) {
            float ex = expf(row[e] - m1);
            row[e] = ex;
            s += ex;
        }
        float inv = 1.0f / s;
#pragma unroll
        for (int e = 0; e < NUM_EXPERTS; e++) row[e] *= inv;

        float p1 = row[e1];
        float p2 = row[e2];
        float r  = expf(p2 - p1);           // combine = softmax([p1,p2])
        float c1 = 1.0f / (1.0f + r);
        float c2 = r * c1;

        int gi = 2 * token;
        g_flat_idx[gi]     = e1;
        g_flat_idx[gi + 1] = e2;
        out[OFF_CW + gi]     = c1;
        out[OFF_CW + gi + 1] = c2;

        atomicAdd(&s_hist[e1], 1);
        atomicAdd(&s_hist[e2], 1);
    }
    __syncthreads();

    // Coalesced probs writeout: 128 x 64 floats
    for (int i = tid; i < BT * NUM_EXPERTS; i += 256) {
        out[OFF_PROBS + (size_t)t0 * NUM_EXPERTS + i] = logits[i >> 6][i & 63];
    }
    if (tid < NUM_EXPERTS) g_hist[b][tid] = s_hist[tid];
}

// ---------------------------------------------------------------------------
// Kernel 2: per-expert chunk-prefix + expert base offsets + input_splits
// ---------------------------------------------------------------------------
__global__ __launch_bounds__(256) void prefix_kernel(float* __restrict__ out)
{
    __shared__ int sh[NBLK * NUM_EXPERTS];   // 32KB
    __shared__ int s_cnt[NUM_EXPERTS];
    __shared__ int s_base[NUM_EXPERTS];
    const int tid = threadIdx.x;

    const int4* src = (const int4*)g_hist;
    int4* dst = (int4*)sh;
    for (int i = tid; i < NBLK * NUM_EXPERTS / 4; i += 256) dst[i] = src[i];
    __syncthreads();

    if (tid < NUM_EXPERTS) {
        int run = 0;
#pragma unroll 8
        for (int c = 0; c < NBLK; c++) run += sh[c * NUM_EXPERTS + tid];
        s_cnt[tid] = run;
    }
    __syncthreads();
    if (tid == 0) {
        int base = 0;
        for (int i = 0; i < NUM_EXPERTS; i++) { s_base[i] = base; base += s_cnt[i]; }
    }
    __syncthreads();
    if (tid < NUM_EXPERTS) {
        out[OFF_SPLITS + tid] = (float)s_cnt[tid];
        int run = s_base[tid];
#pragma unroll 8
        for (int c = 0; c < NBLK; c++) {
            g_offset[c][tid] = run;
            run += sh[c * NUM_EXPERTS + tid];
        }
    }
}

// ---------------------------------------------------------------------------
// Kernel 3: stable scatter via match_any + per-warp histograms
// ---------------------------------------------------------------------------
__global__ __launch_bounds__(CHUNK) void scatter_kernel(float* __restrict__ out)
{
    __shared__ int whist[8][NUM_EXPERTS];
    const int tid  = threadIdx.x;
    const int lane = tid & 31;
    const int w    = tid >> 5;
    const int b    = blockIdx.x;
    const int gi   = b * CHUNK + tid;

    for (int i = tid; i < 8 * NUM_EXPERTS; i += CHUNK) ((int*)whist)[i] = 0;
    __syncthreads();

    const int me = g_flat_idx[gi];
    unsigned mask = __match_any_sync(0xffffffffu, me);
    int before = __popc(mask & ((1u << lane) - 1u));
    if (before == 0) whist[w][me] = __popc(mask);   // lowest matching lane = leader
    __syncthreads();

    int r = before;
#pragma unroll
    for (int ww = 0; ww < 8; ww++)
        if (ww < w) r += whist[ww][me];

    const int pos = g_offset[b][me] + r;
    out[OFF_TOKEN + pos] = (float)(gi >> 1);   // token index
    out[OFF_REV + gi]    = (float)pos;         // reversed ordering
}

// ---------------------------------------------------------------------------
extern "C" void kernel_launch(void* const* d_in, const int* in_sizes, int n_in,
                              void* d_out, int out_size)
{
    const float* X = (const float*)d_in[0];   // inputs [16384, 2048]
    const float* W = (const float*)d_in[1];   // wg_weight [64, 2048]
    float* out = (float*)d_out;

    static int smem_set = 0;
    if (!smem_set) {
        cudaFuncSetAttribute(gate_kernel,
                             cudaFuncAttributeMaxDynamicSharedMemorySize, SMEM_DYN);
        smem_set = 1;
    }

    wconv_kernel<<<128, 256>>>(W);
    gate_kernel<<<NBLK, 256, SMEM_DYN>>>(X, out);
    prefix_kernel<<<1, 256>>>(out);
    scatter_kernel<<<NBLK, CHUNK>>>(out);
}